// round 13
// baseline (speedup 1.0000x reference)
#include <cuda_runtime.h>
#include <cuda_fp16.h>

#define NN 1024
#define DIM 128
#define HH 4
#define I_TILE 8
#define LOG2E 1.4426950408889634f

typedef unsigned long long u64;
typedef unsigned int u32;

// Scratch (device globals: no allocations allowed)
__device__ __half g_Lh[NN * DIM];          // fp16 L, row-major [i][head*32+d]
__device__ __half g_Rh[NN * DIM];          // fp16 R, [head*4+qg][j][8 halves]
__device__ u32    g_Vf[NN * DIM / 2];      // fp16 V in HMMA B-fragment order
__device__ float  g_La6[NN * HH];          // 0.6*log2e * sum_d a_d*L
__device__ float  g_Ra6[NN * HH];
__device__ unsigned char g_adj8[128 * NN]; // byte per (i-block, j): bit ii = adj
__device__ float  g_part[128 * 8 * I_TILE * DIM]; // [iblk][j-eighth][ii][d]
__device__ float  g_Spart[128 * 8 * I_TILE * HH]; // [iblk][j-eighth][ii][h]

#define HADD2(d, x, y) \
    asm("add.rn.f16x2 %0, %1, %2;" : "=r"(d) : "r"(x), "r"(y))
#define HFMA2(acc, m, x) \
    asm("fma.rn.f16x2 %0, %1, %2, %0;" : "+r"(acc) : "r"(m), "r"(x))
#define MMA16816(d0, d1, d2, d3, a0, a1, a2, a3, b0, b1) \
    asm volatile("mma.sync.aligned.m16n8k16.row.col.f32.f16.f16.f32 " \
                 "{%0,%1,%2,%3}, {%4,%5,%6,%7}, {%8,%9}, {%0,%1,%2,%3};" \
                 : "+f"(d0), "+f"(d1), "+f"(d2), "+f"(d3) \
                 : "r"(a0), "r"(a1), "r"(a2), "r"(a3), "r"(b0), "r"(b1))

// ---------------------------------------------------------------------------
// Prep (unchanged from R12): Lh, Rh (transposed), Vf (B-fragment order),
// La6/Ra6 (pre-scaled), adj bit-pack. Grid (128, 4), block 128.
// ---------------------------------------------------------------------------
__global__ __launch_bounds__(128) void prep_kernel(
    const float* __restrict__ h,
    const int*   __restrict__ adj,
    const float* __restrict__ Wl,
    const float* __restrict__ Wr,
    const float* __restrict__ Wv,
    const float* __restrict__ a)
{
    int which = blockIdx.y;
    int tid = threadIdx.x;

    if (which == 3) {                    // adj bit-packing slice
        int i0 = blockIdx.x * 8;
#pragma unroll
        for (int jj = 0; jj < 8; jj++) {
            int j = tid + jj * 128;
            unsigned b = 0;
#pragma unroll
            for (int ii = 0; ii < 8; ii++)
                b |= (__ldg(&adj[(i0 + ii) * NN + j]) != 0 ? 1u : 0u) << ii;
            g_adj8[blockIdx.x * NN + j] = (unsigned char)b;
        }
        return;
    }

    const float* W = (which == 0) ? Wl : (which == 1) ? Wr : Wv;
    int i0 = blockIdx.x * 8;

    __shared__ float h_s[8 * DIM];
#pragma unroll
    for (int q = 0; q < 8; q++)
        h_s[tid + q * 128] = h[i0 * DIM + tid + q * 128];
    __syncthreads();

    float acc[8] = {0.f, 0.f, 0.f, 0.f, 0.f, 0.f, 0.f, 0.f};
    const float4* h4 = reinterpret_cast<const float4*>(h_s);
#pragma unroll 4
    for (int k4 = 0; k4 < 32; k4++) {
        float w0 = __ldg(&W[(k4 * 4 + 0) * DIM + tid]);
        float w1 = __ldg(&W[(k4 * 4 + 1) * DIM + tid]);
        float w2 = __ldg(&W[(k4 * 4 + 2) * DIM + tid]);
        float w3 = __ldg(&W[(k4 * 4 + 3) * DIM + tid]);
#pragma unroll
        for (int r = 0; r < 8; r++) {
            float4 hv = h4[r * 32 + k4];
            acc[r] += hv.x * w0 + hv.y * w1 + hv.z * w2 + hv.w * w3;
        }
    }

    int head = tid >> 5, d = tid & 31;
    if (which == 0) {
#pragma unroll
        for (int r = 0; r < 8; r++)
            g_Lh[(i0 + r) * DIM + tid] = __float2half_rn(acc[r]);
    } else if (which == 1) {
        int qg = d >> 3, slot = d & 7;
        __half* base = &g_Rh[(size_t)((head * 4 + qg) * NN) * 8 + slot];
#pragma unroll
        for (int r = 0; r < 8; r++) base[(i0 + r) * 8] = __float2half_rn(acc[r]);
    } else {
        int dt = d >> 3, n = d & 7;
        int jb = blockIdx.x >> 1, regsel = blockIdx.x & 1;
        u32 base = (((head * 64 + jb) * 4 + dt) * 32 + 4 * n) * 2 + regsel;
#pragma unroll
        for (int m = 0; m < 4; m++) {
            __half2 hp = __floats2half2_rn(acc[2 * m], acc[2 * m + 1]);
            g_Vf[base + m * 2] = *reinterpret_cast<u32*>(&hp);
        }
    }

    if (which < 2) {
        float av = 0.6f * LOG2E * __ldg(&a[d]);
        float* A6 = (which == 0) ? g_La6 : g_Ra6;
#pragma unroll
        for (int r = 0; r < 8; r++) {
            float v = av * acc[r];
#pragma unroll
            for (int o = 16; o; o >>= 1) v += __shfl_xor_sync(0xffffffffu, v, o);
            if (d == 0) A6[(i0 + r) * HH + head] = v;
        }
    }
}

// ---------------------------------------------------------------------------
// Main kernel. Grid 512 = 128 i-blocks x 4 j-quarters; block 256 = 8 warps
// (4 heads x 2 j-subgroups). launch_bounds(256,3) -> up to 24 warps/SM.
// Per t (4 stages of 64 j) warp handles j = q*256 + t*64 + js*32 + lane for
// all 8 i-rows. e-phase fp16x2; agg on tensor pipe (ldmatrix + mma).
// Emits UNNORMALIZED partials (g_part / g_Spart) for its j-eighth; no epilogue.
// ---------------------------------------------------------------------------
__global__ __launch_bounds__(256, 3) void gat_main(
    const float* __restrict__ a,
    float*       __restrict__ dummy)
{
    __shared__ __align__(16) __half l_sh[I_TILE * DIM];         // fp16 l rows
    __shared__ __align__(16) __half p_sh[8 * I_TILE * 32 + 32]; // + zero row
    __shared__ __align__(16) u32    ar_s[16];                   // fp16x2 a-pairs
    __shared__ float la_s[I_TILE * HH];

    int tid  = threadIdx.x;
    int w    = tid >> 5, lane = tid & 31;
    int head = w & 3,    js   = w >> 2;      // js in 0..1
    int iblk = blockIdx.x >> 2;
    int q    = blockIdx.x & 3;               // j-quarter
    int i0   = iblk * I_TILE;

    if (tid < 16) {
        __half2 hp = __floats2half2_rn((0.4f * LOG2E) * __ldg(&a[2 * tid]),
                                       (0.4f * LOG2E) * __ldg(&a[2 * tid + 1]));
        ar_s[tid] = *reinterpret_cast<u32*>(&hp);
    }
    if (tid < 128)       // stage fp16 l rows: 8 x 256B
        reinterpret_cast<uint4*>(l_sh)[tid] =
            __ldg(&reinterpret_cast<const uint4*>(g_Lh)[i0 * (DIM / 8) + tid]);
    if (tid < I_TILE * HH)
        la_s[tid] = __ldg(&g_La6[i0 * HH + tid]);
    if (tid < 16)        // zero row for ldmatrix M-padding
        reinterpret_cast<u32*>(p_sh + 8 * 256)[tid] = 0u;

    float sl[I_TILE];
    float dacc[16];
#pragma unroll
    for (int ii = 0; ii < I_TILE; ii++) sl[ii] = 0.f;
#pragma unroll
    for (int k = 0; k < 16; k++) dacc[k] = 0.f;
    __syncthreads();

    const uint4* Rh4 = reinterpret_cast<const uint4*>(g_Rh);
    __half* myph = &p_sh[w * 256];
    int lg = lane >> 3, lr = lane & 7;       // ldmatrix tile group / row

    for (int t = 0; t < 4; t++) {
        int jcol = q * 256 + t * 64 + js * 32 + lane;  // this lane's j
        int jb0  = q * 16 + t * 4 + js * 2;            // first 16-j block

        // ---- stage-top loads: r, ra, adj, B-fragments (all L2 hits) ----
        uint4 r4[4];
#pragma unroll
        for (int qg = 0; qg < 4; qg++)
            r4[qg] = __ldg(&Rh4[(head * 4 + qg) * NN + jcol]);
        float ra = __ldg(&g_Ra6[jcol * HH + head]);
        unsigned b = __ldg(&g_adj8[iblk * NN + jcol]);
        uint2 bq[8];
#pragma unroll
        for (int ks = 0; ks < 2; ks++)
#pragma unroll
            for (int nt = 0; nt < 4; nt++)
                bq[ks * 4 + nt] = __ldg(reinterpret_cast<const uint2*>(
                    &g_Vf[(((head * 64 + jb0 + ks) * 4 + nt) * 32 + lane) * 2]));

        // ---- e phase: fp16x2 HADD2 + abs(LOP) + HFMA2 ----
#pragma unroll
        for (int ii = 0; ii < I_TILE; ii++) {
            const uint4* lrow = reinterpret_cast<const uint4*>(&l_sh[ii * DIM + head * 32]);
            const uint4* arp  = reinterpret_cast<const uint4*>(ar_s);
            u32 ea0 = 0u, ea1 = 0u, ea2 = 0u, ea3 = 0u;
#pragma unroll
            for (int qg = 0; qg < 4; qg++) {
                uint4 l4 = lrow[qg];
                uint4 ar4 = arp[qg];
                u32 y0, y1, y2, y3;
                HADD2(y0, l4.x, r4[qg].x);
                HADD2(y1, l4.y, r4[qg].y);
                HADD2(y2, l4.z, r4[qg].z);
                HADD2(y3, l4.w, r4[qg].w);
                y0 &= 0x7FFF7FFFu; y1 &= 0x7FFF7FFFu;   // |.| both halves (ALU)
                y2 &= 0x7FFF7FFFu; y3 &= 0x7FFF7FFFu;
                HFMA2(ea0, ar4.x, y0);
                HFMA2(ea1, ar4.y, y1);
                HFMA2(ea2, ar4.z, y2);
                HFMA2(ea3, ar4.w, y3);
            }
            HADD2(ea0, ea0, ea1);
            HADD2(ea2, ea2, ea3);
            HADD2(ea0, ea0, ea2);
            float2 f2 = __half22float2(*reinterpret_cast<__half2*>(&ea0));
            float e = (la_s[ii * HH + head] + ra) + (f2.x + f2.y);
            float p;
            asm("ex2.approx.f32 %0, %1;" : "=f"(p) : "f"(e));
            p = (b & (1u << ii)) ? p : 0.f;
            sl[ii] += p;
            myph[ii * 32 + lane] = __float2half_rn(p);
        }
        __syncwarp();

        // ---- agg phase on tensor pipe: ldmatrix + mma.m16n8k16 ----
#pragma unroll
        for (int ks = 0; ks < 2; ks++) {
            const __half* ap = (lg & 1) ? (p_sh + 8 * 256)
                                        : (myph + lr * 32 + ks * 16 + (lg >> 1) * 8);
            u32 sa = (u32)__cvta_generic_to_shared(ap);
            u32 a0, a1, a2, a3;
            asm volatile("ldmatrix.sync.aligned.m8n8.x4.shared.b16 {%0,%1,%2,%3}, [%4];"
                         : "=r"(a0), "=r"(a1), "=r"(a2), "=r"(a3) : "r"(sa));
#pragma unroll
            for (int nt = 0; nt < 4; nt++)
                MMA16816(dacc[nt * 4 + 0], dacc[nt * 4 + 1],
                         dacc[nt * 4 + 2], dacc[nt * 4 + 3],
                         a0, a1, a2, a3, bq[ks * 4 + nt].x, bq[ks * 4 + nt].y);
        }
        __syncwarp();   // LDSM consumed before next stage's STS overwrites p
    }

    // ---- emit partials for this j-eighth (q*2 + js); no barriers needed ----
    int eighth = iblk * 8 + q * 2 + js;
#pragma unroll
    for (int ii = 0; ii < I_TILE; ii++) {
        float S = sl[ii];
#pragma unroll
        for (int o = 16; o; o >>= 1) S += __shfl_xor_sync(0xffffffffu, S, o);
        if (lane == 0) g_Spart[(eighth * I_TILE + ii) * HH + head] = S;
    }
    {
        int iw = lane >> 2, db = 2 * (lane & 3);
        float* base = &g_part[(eighth * I_TILE + iw) * DIM + head * 32];
#pragma unroll
        for (int nt = 0; nt < 4; nt++) {
            float2 v = make_float2(dacc[nt * 4 + 0], dacc[nt * 4 + 1]);
            *reinterpret_cast<float2*>(&base[nt * 8 + db]) = v;
        }
    }
    (void)dummy;
}

// ---------------------------------------------------------------------------
// Final combine: sum 8 j-eighth partials, softmax-normalize, LayerNorm, ReLU.
// Grid 128 (i-blocks), block 256: warp ii handles row i0+ii; lane owns 4 d.
// ---------------------------------------------------------------------------
__global__ __launch_bounds__(256) void ln_final(
    const float* __restrict__ ln_g,
    const float* __restrict__ ln_b,
    float*       __restrict__ out)
{
    int iblk = blockIdx.x;
    int tid = threadIdx.x;
    int ii = tid >> 5, lane = tid & 31;
    int h = lane >> 3;                       // head of this lane's d-range

    float4 agg = make_float4(0.f, 0.f, 0.f, 0.f);
    float S = 0.f;
#pragma unroll
    for (int e = 0; e < 8; e++) {
        float4 p = __ldg(reinterpret_cast<const float4*>(
            &g_part[((iblk * 8 + e) * I_TILE + ii) * DIM + lane * 4]));
        agg.x += p.x; agg.y += p.y; agg.z += p.z; agg.w += p.w;
        S += __ldg(&g_Spart[((iblk * 8 + e) * I_TILE + ii) * HH + h]);
    }
    float inv = __frcp_rn(S);
    float v0 = agg.x * inv, v1 = agg.y * inv, v2 = agg.z * inv, v3 = agg.w * inv;

    float sm = (v0 + v1) + (v2 + v3);
    float sq = v0 * v0 + v1 * v1 + v2 * v2 + v3 * v3;
#pragma unroll
    for (int o = 16; o; o >>= 1) {
        sm += __shfl_xor_sync(0xffffffffu, sm, o);
        sq += __shfl_xor_sync(0xffffffffu, sq, o);
    }
    float mean = sm * (1.f / 128.f);
    float var  = sq * (1.f / 128.f) - mean * mean;
    float rstd = rsqrtf(var + 1e-5f);

    float4 gg = __ldg(reinterpret_cast<const float4*>(&ln_g[lane * 4]));
    float4 bb = __ldg(reinterpret_cast<const float4*>(&ln_b[lane * 4]));
    float4 y;
    y.x = fmaxf((v0 - mean) * rstd * gg.x + bb.x, 0.f);
    y.y = fmaxf((v1 - mean) * rstd * gg.y + bb.y, 0.f);
    y.z = fmaxf((v2 - mean) * rstd * gg.z + bb.z, 0.f);
    y.w = fmaxf((v3 - mean) * rstd * gg.w + bb.w, 0.f);
    *reinterpret_cast<float4*>(&out[(iblk * I_TILE + ii) * DIM + lane * 4]) = y;
}

extern "C" void kernel_launch(void* const* d_in, const int* in_sizes, int n_in,
                              void* d_out, int out_size)
{
    const float* h   = (const float*)d_in[0];
    const int*   adj = (const int*)  d_in[1];
    const float* Wl  = (const float*)d_in[2];
    const float* Wr  = (const float*)d_in[3];
    const float* Wv  = (const float*)d_in[4];
    const float* a   = (const float*)d_in[5];
    const float* g   = (const float*)d_in[6];
    const float* b   = (const float*)d_in[7];

    prep_kernel<<<dim3(128, 4), 128>>>(h, adj, Wl, Wr, Wv, a);
    gat_main<<<512, 256>>>(a, (float*)d_out);
    ln_final<<<128, 256>>>(g, b, (float*)d_out);
}

// round 14
// speedup vs baseline: 1.1308x; 1.1308x over previous
#include <cuda_runtime.h>
#include <cuda_fp16.h>

#define NN 1024
#define DIM 128
#define HH 4
#define I_TILE 8
#define LOG2E 1.4426950408889634f

typedef unsigned long long u64;
typedef unsigned int u32;

// Scratch (device globals: no allocations allowed)
__device__ __half g_Lh[NN * DIM];          // fp16 L, row-major [i][head*32+d]
__device__ __half g_Rh[NN * DIM];          // fp16 R, [head*4+qg][j][8 halves]
__device__ u32    g_Vf[NN * DIM / 2];      // fp16 V in HMMA B-fragment order
__device__ float  g_La6[NN * HH];          // 0.6*log2e * sum_d a_d*L
__device__ float  g_Ra6[NN * HH];
__device__ unsigned char g_adj8[128 * NN]; // byte per (i-block, j): bit ii = adj

#define HADD2(d, x, y) \
    asm("add.rn.f16x2 %0, %1, %2;" : "=r"(d) : "r"(x), "r"(y))
#define HFMA2(acc, m, x) \
    asm("fma.rn.f16x2 %0, %1, %2, %0;" : "+r"(acc) : "r"(m), "r"(x))
#define MMA16816(d0, d1, d2, d3, a0, a1, a2, a3, b0, b1) \
    asm volatile("mma.sync.aligned.m16n8k16.row.col.f32.f16.f16.f32 " \
                 "{%0,%1,%2,%3}, {%4,%5,%6,%7}, {%8,%9}, {%0,%1,%2,%3};" \
                 : "+f"(d0), "+f"(d1), "+f"(d2), "+f"(d3) \
                 : "r"(a0), "r"(a1), "r"(a2), "r"(a3), "r"(b0), "r"(b1))

// ---------------------------------------------------------------------------
// Prep: 16 rows/CTA for high ILP (4 W-loads feed 64 FMAs per k4 step).
// y=0: Lh = fp16(h@W_l); y=1: Rh transposed; y=2: Vf (B-fragment order);
// plus La6/Ra6 (pre-scaled by 0.6*log2e). y=3: pack adj bits (2 i-blocks/CTA).
// Grid (64, 4), block 128.
// ---------------------------------------------------------------------------
__global__ __launch_bounds__(128) void prep_kernel(
    const float* __restrict__ h,
    const int*   __restrict__ adj,
    const float* __restrict__ Wl,
    const float* __restrict__ Wr,
    const float* __restrict__ Wv,
    const float* __restrict__ a)
{
    int which = blockIdx.y;
    int tid = threadIdx.x;

    if (which == 3) {                    // adj bit-packing: 2 i-blocks per CTA
#pragma unroll
        for (int ib = 0; ib < 2; ib++) {
            int iblk = blockIdx.x * 2 + ib;
            int i0 = iblk * 8;
#pragma unroll
            for (int jj = 0; jj < 8; jj++) {
                int j = tid + jj * 128;
                unsigned b = 0;
#pragma unroll
                for (int ii = 0; ii < 8; ii++)
                    b |= (__ldg(&adj[(i0 + ii) * NN + j]) != 0 ? 1u : 0u) << ii;
                g_adj8[iblk * NN + j] = (unsigned char)b;
            }
        }
        return;
    }

    const float* W = (which == 0) ? Wl : (which == 1) ? Wr : Wv;
    int i0 = blockIdx.x * 16;

    __shared__ float h_s[16 * DIM];
#pragma unroll
    for (int q = 0; q < 16; q++)
        h_s[tid + q * 128] = h[i0 * DIM + tid + q * 128];
    __syncthreads();

    float acc[16];
#pragma unroll
    for (int r = 0; r < 16; r++) acc[r] = 0.f;

    const float4* h4 = reinterpret_cast<const float4*>(h_s);
#pragma unroll 4
    for (int k4 = 0; k4 < 32; k4++) {
        float w0 = __ldg(&W[(k4 * 4 + 0) * DIM + tid]);
        float w1 = __ldg(&W[(k4 * 4 + 1) * DIM + tid]);
        float w2 = __ldg(&W[(k4 * 4 + 2) * DIM + tid]);
        float w3 = __ldg(&W[(k4 * 4 + 3) * DIM + tid]);
#pragma unroll
        for (int r = 0; r < 16; r++) {
            float4 hv = h4[r * 32 + k4];
            acc[r] += hv.x * w0 + hv.y * w1 + hv.z * w2 + hv.w * w3;
        }
    }

    int head = tid >> 5, d = tid & 31;
    if (which == 0) {
#pragma unroll
        for (int r = 0; r < 16; r++)
            g_Lh[(i0 + r) * DIM + tid] = __float2half_rn(acc[r]);
    } else if (which == 1) {
        int qg = d >> 3, slot = d & 7;
        __half* base = &g_Rh[(size_t)((head * 4 + qg) * NN) * 8 + slot];
#pragma unroll
        for (int r = 0; r < 16; r++) base[(i0 + r) * 8] = __float2half_rn(acc[r]);
    } else {
        // B-fragment store: CTA covers the whole 16-j block jb = blockIdx.x.
        // lane l = 4n+m, register regsel holds {V[regsel*8+2m][n], V[..+1][n]}.
        int dt = d >> 3, n = d & 7;
        int jb = blockIdx.x;
#pragma unroll
        for (int regsel = 0; regsel < 2; regsel++)
#pragma unroll
            for (int m = 0; m < 4; m++) {
                __half2 hp = __floats2half2_rn(acc[regsel * 8 + 2 * m],
                                               acc[regsel * 8 + 2 * m + 1]);
                g_Vf[(((head * 64 + jb) * 4 + dt) * 32 + 4 * n + m) * 2 + regsel] =
                    *reinterpret_cast<u32*>(&hp);
            }
    }

    if (which < 2) {
        float av = 0.6f * LOG2E * __ldg(&a[d]);
        float* A6 = (which == 0) ? g_La6 : g_Ra6;
#pragma unroll
        for (int r = 0; r < 16; r++) {
            float v = av * acc[r];
#pragma unroll
            for (int o = 16; o; o >>= 1) v += __shfl_xor_sync(0xffffffffu, v, o);
            if (d == 0) A6[(i0 + r) * HH + head] = v;
        }
    }
}

// ---------------------------------------------------------------------------
// Main fused kernel (R12 structure + cross-stage r-prefetch).
// Grid 128 (I_TILE=8 rows each), block 512 = 16 warps.
// Warp w: head = w&3, js = w>>2; per t handles j = t*128+js*32+lane, all 8 i.
// r4/ra/adj for stage t+1 are issued before e-phase(t) (one full e-phase of
// slack -> L2 latency fully hidden). bq(t) loads hide behind e-phase(t).
// e-phase fp16x2; agg on tensor pipe (ldmatrix + mma.m16n8k16, fp32 accum).
// Max-free base-2 softmax; mask -> p = 0.
// ---------------------------------------------------------------------------
__global__ __launch_bounds__(512) void gat_main(
    const float* __restrict__ a,
    const float* __restrict__ ln_g,
    const float* __restrict__ ln_b,
    float*       __restrict__ out)
{
    __shared__ __align__(16) __half l_sh[I_TILE * DIM];       // fp16 l rows
    __shared__ __align__(16) __half p_sh[16 * I_TILE * 32 + 32]; // + zero row
    __shared__ __align__(16) float  red_s[16 * I_TILE * 32];  // cross-warp acc
    __shared__ __align__(16) float  o_s[I_TILE * DIM];
    __shared__ float sl_s[16 * I_TILE];

    int tid  = threadIdx.x;
    int w    = tid >> 5, lane = tid & 31;
    int head = w & 3,    js   = w >> 2;      // js in 0..3
    int i0   = blockIdx.x * I_TILE;

    // 0.4*log2e * a packed as 16 fp16x2 (d-pairs), warp-uniform in regs
    u32 ar2h[16];
#pragma unroll
    for (int s = 0; s < 16; s++) {
        __half2 hp = __floats2half2_rn((0.4f * LOG2E) * __ldg(&a[2 * s]),
                                       (0.4f * LOG2E) * __ldg(&a[2 * s + 1]));
        ar2h[s] = *reinterpret_cast<u32*>(&hp);
    }

    if (tid < 128)       // stage fp16 l rows: 8 x 256B
        reinterpret_cast<uint4*>(l_sh)[tid] =
            __ldg(&reinterpret_cast<const uint4*>(g_Lh)[i0 * (DIM / 8) + tid]);
    if (tid < 16)        // zero row for ldmatrix M-padding
        reinterpret_cast<u32*>(p_sh + 16 * 256)[tid] = 0u;

    float la[I_TILE], sl[I_TILE];
    float dacc[16];
#pragma unroll
    for (int ii = 0; ii < I_TILE; ii++) {
        la[ii] = __ldg(&g_La6[(i0 + ii) * HH + head]);
        sl[ii] = 0.f;
    }
#pragma unroll
    for (int k = 0; k < 16; k++) dacc[k] = 0.f;
    __syncthreads();   // l_sh + zero row visible

    const uint4* Rh4 = reinterpret_cast<const uint4*>(g_Rh);
    __half* myph = &p_sh[w * 256];
    int lg = lane >> 3, lr = lane & 7;       // ldmatrix tile group / row

    // preload r-side for stage 0
    uint4 r4[4];
    float ra;
    unsigned b;
    {
        int jcol = js * 32 + lane;
#pragma unroll
        for (int qg = 0; qg < 4; qg++)
            r4[qg] = __ldg(&Rh4[(head * 4 + qg) * NN + jcol]);
        ra = __ldg(&g_Ra6[jcol * HH + head]);
        b  = __ldg(&g_adj8[blockIdx.x * NN + jcol]);
    }

    for (int t = 0; t < 8; t++) {
        int jb0 = t * 8 + js * 2;                // first 16-j block

        // ---- B-fragment loads for stage t (consumed after e-phase: hidden) ----
        uint2 bq[8];
#pragma unroll
        for (int ks = 0; ks < 2; ks++)
#pragma unroll
            for (int nt = 0; nt < 4; nt++)
                bq[ks * 4 + nt] = __ldg(reinterpret_cast<const uint2*>(
                    &g_Vf[(((head * 64 + jb0 + ks) * 4 + nt) * 32 + lane) * 2]));

        // ---- prefetch r-side for stage t+1 (consumed one e-phase later) ----
        uint4 r4n[4];
        float ran = 0.f;
        unsigned bn = 0;
        if (t < 7) {
            int jn = (t + 1) * 128 + js * 32 + lane;
#pragma unroll
            for (int qg = 0; qg < 4; qg++)
                r4n[qg] = __ldg(&Rh4[(head * 4 + qg) * NN + jn]);
            ran = __ldg(&g_Ra6[jn * HH + head]);
            bn  = __ldg(&g_adj8[blockIdx.x * NN + jn]);
        }

        // ---- e phase: fp16x2 HADD2 + abs(LOP) + HFMA2 ----
#pragma unroll
        for (int ii = 0; ii < I_TILE; ii++) {
            const uint4* lrow = reinterpret_cast<const uint4*>(&l_sh[ii * DIM + head * 32]);
            u32 ea0 = 0u, ea1 = 0u, ea2 = 0u, ea3 = 0u;   // half2 zeros
#pragma unroll
            for (int qg = 0; qg < 4; qg++) {
                uint4 l4 = lrow[qg];
                u32 y0, y1, y2, y3;
                HADD2(y0, l4.x, r4[qg].x);
                HADD2(y1, l4.y, r4[qg].y);
                HADD2(y2, l4.z, r4[qg].z);
                HADD2(y3, l4.w, r4[qg].w);
                y0 &= 0x7FFF7FFFu; y1 &= 0x7FFF7FFFu;     // |.| both halves (ALU)
                y2 &= 0x7FFF7FFFu; y3 &= 0x7FFF7FFFu;
                HFMA2(ea0, ar2h[qg * 4 + 0], y0);
                HFMA2(ea1, ar2h[qg * 4 + 1], y1);
                HFMA2(ea2, ar2h[qg * 4 + 2], y2);
                HFMA2(ea3, ar2h[qg * 4 + 3], y3);
            }
            HADD2(ea0, ea0, ea1);
            HADD2(ea2, ea2, ea3);
            HADD2(ea0, ea0, ea2);
            float2 f2 = __half22float2(*reinterpret_cast<__half2*>(&ea0));
            float e = (la[ii] + ra) + (f2.x + f2.y);
            float p;
            asm("ex2.approx.f32 %0, %1;" : "=f"(p) : "f"(e));
            p = (b & (1u << ii)) ? p : 0.f;
            sl[ii] += p;
            myph[ii * 32 + lane] = __float2half_rn(p);
        }
        __syncwarp();

        // ---- agg phase on tensor pipe: ldmatrix + mma.m16n8k16 ----
#pragma unroll
        for (int ks = 0; ks < 2; ks++) {
            const __half* ap = (lg & 1) ? (p_sh + 16 * 256)
                                        : (myph + lr * 32 + ks * 16 + (lg >> 1) * 8);
            u32 sa = (u32)__cvta_generic_to_shared(ap);
            u32 a0, a1, a2, a3;
            asm volatile("ldmatrix.sync.aligned.m8n8.x4.shared.b16 {%0,%1,%2,%3}, [%4];"
                         : "=r"(a0), "=r"(a1), "=r"(a2), "=r"(a3) : "r"(sa));
#pragma unroll
            for (int nt = 0; nt < 4; nt++)
                MMA16816(dacc[nt * 4 + 0], dacc[nt * 4 + 1],
                         dacc[nt * 4 + 2], dacc[nt * 4 + 3],
                         a0, a1, a2, a3, bq[ks * 4 + nt].x, bq[ks * 4 + nt].y);
        }
        __syncwarp();   // LDSM consumed before next stage's STS overwrites p

        // rotate prefetched r-side into place
        if (t < 7) {
#pragma unroll
            for (int qg = 0; qg < 4; qg++) r4[qg] = r4n[qg];
            ra = ran;
            b  = bn;
        }
    }

    // ---- cross-warp (js) reduction ----
#pragma unroll
    for (int ii = 0; ii < I_TILE; ii++) {
        float S = sl[ii];
#pragma unroll
        for (int o = 16; o; o >>= 1) S += __shfl_xor_sync(0xffffffffu, S, o);
        if (lane == 0) sl_s[w * I_TILE + ii] = S;
    }
    // write mma accumulators: lane holds (ii = lane/4, d = nt*8 + 2*(lane%4)+{0,1})
    {
        int iw = lane >> 2, db = 2 * (lane & 3);
        float* myred = &red_s[w * 256];
#pragma unroll
        for (int nt = 0; nt < 4; nt++) {
            myred[iw * 32 + nt * 8 + db]     = dacc[nt * 4 + 0];
            myred[iw * 32 + nt * 8 + db + 1] = dacc[nt * 4 + 1];
        }
    }
    __syncthreads();

    // warp w: head' = w&3, covers ii = (w>>2) and (w>>2)+4
#pragma unroll
    for (int r = 0; r < 2; r++) {
        int ii = (w >> 2) + r * 4;
        int hh = w & 3;
        float acc = 0.f, S = 0.f;
#pragma unroll
        for (int g = 0; g < 4; g++) {
            acc += red_s[((g * 4 + hh) * I_TILE + ii) * 32 + lane];
            S   += sl_s[(g * 4 + hh) * I_TILE + ii];
        }
        o_s[ii * DIM + hh * 32 + lane] = acc * __frcp_rn(S);
    }
    __syncthreads();

    // LayerNorm + ReLU: warps 0..7 handle rows 0..7
    if (w < I_TILE) {
        int i = w;
        float v0 = o_s[i * DIM + lane];
        float v1 = o_s[i * DIM + 32 + lane];
        float v2 = o_s[i * DIM + 64 + lane];
        float v3 = o_s[i * DIM + 96 + lane];
        float sm = (v0 + v1) + (v2 + v3);
        float sq = v0 * v0 + v1 * v1 + v2 * v2 + v3 * v3;
#pragma unroll
        for (int o = 16; o; o >>= 1) {
            sm += __shfl_xor_sync(0xffffffffu, sm, o);
            sq += __shfl_xor_sync(0xffffffffu, sq, o);
        }
        float mean = sm * (1.f / 128.f);
        float var  = sq * (1.f / 128.f) - mean * mean;
        float rstd = rsqrtf(var + 1e-5f);
        float vals[4] = {v0, v1, v2, v3};
#pragma unroll
        for (int k = 0; k < 4; k++) {
            int c = 32 * k + lane;
            float y = (vals[k] - mean) * rstd * __ldg(&ln_g[c]) + __ldg(&ln_b[c]);
            out[(i0 + i) * DIM + c] = fmaxf(y, 0.f);
        }
    }
}

extern "C" void kernel_launch(void* const* d_in, const int* in_sizes, int n_in,
                              void* d_out, int out_size)
{
    const float* h   = (const float*)d_in[0];
    const int*   adj = (const int*)  d_in[1];
    const float* Wl  = (const float*)d_in[2];
    const float* Wr  = (const float*)d_in[3];
    const float* Wv  = (const float*)d_in[4];
    const float* a   = (const float*)d_in[5];
    const float* g   = (const float*)d_in[6];
    const float* b   = (const float*)d_in[7];

    prep_kernel<<<dim3(64, 4), 128>>>(h, adj, Wl, Wr, Wv, a);
    gat_main<<<NN / I_TILE, 512>>>(a, g, b, (float*)d_out);
}

// round 15
// speedup vs baseline: 1.2049x; 1.0656x over previous
#include <cuda_runtime.h>
#include <cuda_fp16.h>

#define NN 1024
#define DIM 128
#define HH 4
#define I_TILE 8
#define LOG2E 1.4426950408889634f

typedef unsigned long long u64;
typedef unsigned int u32;

// Scratch (device globals: no allocations allowed)
__device__ __half g_Lh[NN * DIM];          // fp16 L, row-major [i][head*32+d]
__device__ __half g_Rh[NN * DIM];          // fp16 R, [head*4+qg][j][8 halves]
__device__ u32    g_Vf[NN * DIM / 2];      // fp16 V in HMMA B-fragment order
__device__ float  g_La6[NN * HH];          // 0.6*log2e * sum_d a_d*L
__device__ float  g_Ra6[NN * HH];

#define HADD2(d, x, y) \
    asm("add.rn.f16x2 %0, %1, %2;" : "=r"(d) : "r"(x), "r"(y))
#define HFMA2(acc, m, x) \
    asm("fma.rn.f16x2 %0, %1, %2, %0;" : "+r"(acc) : "r"(m), "r"(x))
#define MMA16816(d0, d1, d2, d3, a0, a1, a2, a3, b0, b1) \
    asm volatile("mma.sync.aligned.m16n8k16.row.col.f32.f16.f16.f32 " \
                 "{%0,%1,%2,%3}, {%4,%5,%6,%7}, {%8,%9}, {%0,%1,%2,%3};" \
                 : "+f"(d0), "+f"(d1), "+f"(d2), "+f"(d3) \
                 : "r"(a0), "r"(a1), "r"(a2), "r"(a3), "r"(b0), "r"(b1))

// ---------------------------------------------------------------------------
// Prep: 16 rows/CTA, W fully staged in dynamic smem (64KB) so the k-loop is
// pure LDS+FFMA (no gmem latency). y=0: Lh; y=1: Rh transposed; y=2: Vf;
// plus La6/Ra6 (pre-scaled by 0.6*log2e). Grid (64, 3), block 128.
// Dynamic smem: W_s[128*128] fp32 (64KB) + h_s[16*128] fp32 (8KB) = 72KB.
// ---------------------------------------------------------------------------
__global__ __launch_bounds__(128) void prep_kernel(
    const float* __restrict__ h,
    const float* __restrict__ Wl,
    const float* __restrict__ Wr,
    const float* __restrict__ Wv,
    const float* __restrict__ a)
{
    extern __shared__ float smem[];
    float* W_s = smem;                 // [128][128]
    float* h_s = smem + DIM * DIM;     // [16][128]

    int which = blockIdx.y;
    int tid = threadIdx.x;
    const float* W = (which == 0) ? Wl : (which == 1) ? Wr : Wv;
    int i0 = blockIdx.x * 16;

    // stage W (16384 floats = 4096 float4; 32 per thread) + h (512 float4)
    {
        const float4* W4 = reinterpret_cast<const float4*>(W);
        float4* Ws4 = reinterpret_cast<float4*>(W_s);
#pragma unroll
        for (int q = 0; q < 32; q++)
            Ws4[tid + q * 128] = __ldg(&W4[tid + q * 128]);
        const float4* h4g = reinterpret_cast<const float4*>(h + i0 * DIM);
        float4* hs4 = reinterpret_cast<float4*>(h_s);
#pragma unroll
        for (int q = 0; q < 4; q++)
            hs4[tid + q * 128] = __ldg(&h4g[tid + q * 128]);
    }
    __syncthreads();

    float acc[16];
#pragma unroll
    for (int r = 0; r < 16; r++) acc[r] = 0.f;

    const float4* h4 = reinterpret_cast<const float4*>(h_s);
#pragma unroll 4
    for (int k4 = 0; k4 < 32; k4++) {
        float w0 = W_s[(k4 * 4 + 0) * DIM + tid];
        float w1 = W_s[(k4 * 4 + 1) * DIM + tid];
        float w2 = W_s[(k4 * 4 + 2) * DIM + tid];
        float w3 = W_s[(k4 * 4 + 3) * DIM + tid];
#pragma unroll
        for (int r = 0; r < 16; r++) {
            float4 hv = h4[r * 32 + k4];
            acc[r] += hv.x * w0 + hv.y * w1 + hv.z * w2 + hv.w * w3;
        }
    }

    int head = tid >> 5, d = tid & 31;
    if (which == 0) {
#pragma unroll
        for (int r = 0; r < 16; r++)
            g_Lh[(i0 + r) * DIM + tid] = __float2half_rn(acc[r]);
    } else if (which == 1) {
        int qg = d >> 3, slot = d & 7;
        __half* base = &g_Rh[(size_t)((head * 4 + qg) * NN) * 8 + slot];
#pragma unroll
        for (int r = 0; r < 16; r++) base[(i0 + r) * 8] = __float2half_rn(acc[r]);
    } else {
        // B-fragment store: CTA covers the whole 16-j block jb = blockIdx.x.
        // lane l = 4n+m, register regsel holds {V[regsel*8+2m][n], V[..+1][n]}.
        int dt = d >> 3, n = d & 7;
        int jb = blockIdx.x;
#pragma unroll
        for (int regsel = 0; regsel < 2; regsel++)
#pragma unroll
            for (int m = 0; m < 4; m++) {
                __half2 hp = __floats2half2_rn(acc[regsel * 8 + 2 * m],
                                               acc[regsel * 8 + 2 * m + 1]);
                g_Vf[(((head * 64 + jb) * 4 + dt) * 32 + 4 * n + m) * 2 + regsel] =
                    *reinterpret_cast<u32*>(&hp);
            }
    }

    if (which < 2) {
        float av = 0.6f * LOG2E * __ldg(&a[d]);
        float* A6 = (which == 0) ? g_La6 : g_Ra6;
#pragma unroll
        for (int r = 0; r < 16; r++) {
            float v = av * acc[r];
#pragma unroll
            for (int o = 16; o; o >>= 1) v += __shfl_xor_sync(0xffffffffu, v, o);
            if (d == 0) A6[(i0 + r) * HH + head] = v;
        }
    }
}

// ---------------------------------------------------------------------------
// Main fused kernel (R14 structure; adjacency packed in-prologue to smem).
// Grid 128 (I_TILE=8 rows each), block 512 = 16 warps.
// Warp w: head = w&3, js = w>>2; per t handles j = t*128+js*32+lane, all 8 i.
// r4/ra for stage t+1 prefetched before e-phase(t); adj mask from adj8_s
// (LDS.U8). e-phase fp16x2; agg on tensor pipe (ldmatrix + mma.m16n8k16).
// Max-free base-2 softmax; mask -> p = 0.
// ---------------------------------------------------------------------------
__global__ __launch_bounds__(512) void gat_main(
    const int*   __restrict__ adj,
    const float* __restrict__ a,
    const float* __restrict__ ln_g,
    const float* __restrict__ ln_b,
    float*       __restrict__ out)
{
    __shared__ __align__(16) __half l_sh[I_TILE * DIM];       // fp16 l rows
    __shared__ __align__(16) __half p_sh[16 * I_TILE * 32 + 32]; // + zero row
    __shared__ __align__(16) float  red_s[16 * I_TILE * 32];  // cross-warp acc
    __shared__ __align__(16) float  o_s[I_TILE * DIM];
    __shared__ float sl_s[16 * I_TILE];
    __shared__ unsigned char adj8_s[NN];                      // bit ii = adj

    int tid  = threadIdx.x;
    int w    = tid >> 5, lane = tid & 31;
    int head = w & 3,    js   = w >> 2;      // js in 0..3
    int i0   = blockIdx.x * I_TILE;

    // ---- pack this i-block's adjacency: 2 j per thread, coalesced ----
#pragma unroll
    for (int jj = 0; jj < 2; jj++) {
        int j = tid + jj * 512;
        unsigned bb = 0;
#pragma unroll
        for (int ii = 0; ii < 8; ii++)
            bb |= (__ldg(&adj[(i0 + ii) * NN + j]) != 0 ? 1u : 0u) << ii;
        adj8_s[j] = (unsigned char)bb;
    }

    // 0.4*log2e * a packed as 16 fp16x2 (d-pairs), warp-uniform in regs
    u32 ar2h[16];
#pragma unroll
    for (int s = 0; s < 16; s++) {
        __half2 hp = __floats2half2_rn((0.4f * LOG2E) * __ldg(&a[2 * s]),
                                       (0.4f * LOG2E) * __ldg(&a[2 * s + 1]));
        ar2h[s] = *reinterpret_cast<u32*>(&hp);
    }

    if (tid < 128)       // stage fp16 l rows: 8 x 256B
        reinterpret_cast<uint4*>(l_sh)[tid] =
            __ldg(&reinterpret_cast<const uint4*>(g_Lh)[i0 * (DIM / 8) + tid]);
    if (tid < 16)        // zero row for ldmatrix M-padding
        reinterpret_cast<u32*>(p_sh + 16 * 256)[tid] = 0u;

    float la[I_TILE], sl[I_TILE];
    float dacc[16];
#pragma unroll
    for (int ii = 0; ii < I_TILE; ii++) {
        la[ii] = __ldg(&g_La6[(i0 + ii) * HH + head]);
        sl[ii] = 0.f;
    }
#pragma unroll
    for (int k = 0; k < 16; k++) dacc[k] = 0.f;
    __syncthreads();   // l_sh + zero row + adj8_s visible

    const uint4* Rh4 = reinterpret_cast<const uint4*>(g_Rh);
    __half* myph = &p_sh[w * 256];
    int lg = lane >> 3, lr = lane & 7;       // ldmatrix tile group / row

    // preload r-side for stage 0
    uint4 r4[4];
    float ra;
    {
        int jcol = js * 32 + lane;
#pragma unroll
        for (int qg = 0; qg < 4; qg++)
            r4[qg] = __ldg(&Rh4[(head * 4 + qg) * NN + jcol]);
        ra = __ldg(&g_Ra6[jcol * HH + head]);
    }

    for (int t = 0; t < 8; t++) {
        int jcol = t * 128 + js * 32 + lane;
        int jb0  = t * 8 + js * 2;               // first 16-j block
        unsigned b = adj8_s[jcol];               // LDS.U8

        // ---- B-fragment loads for stage t (consumed after e-phase: hidden) ----
        uint2 bq[8];
#pragma unroll
        for (int ks = 0; ks < 2; ks++)
#pragma unroll
            for (int nt = 0; nt < 4; nt++)
                bq[ks * 4 + nt] = __ldg(reinterpret_cast<const uint2*>(
                    &g_Vf[(((head * 64 + jb0 + ks) * 4 + nt) * 32 + lane) * 2]));

        // ---- prefetch r-side for stage t+1 (consumed one e-phase later) ----
        uint4 r4n[4];
        float ran = 0.f;
        if (t < 7) {
            int jn = (t + 1) * 128 + js * 32 + lane;
#pragma unroll
            for (int qg = 0; qg < 4; qg++)
                r4n[qg] = __ldg(&Rh4[(head * 4 + qg) * NN + jn]);
            ran = __ldg(&g_Ra6[jn * HH + head]);
        }

        // ---- e phase: fp16x2 HADD2 + abs(LOP) + HFMA2 ----
#pragma unroll
        for (int ii = 0; ii < I_TILE; ii++) {
            const uint4* lrow = reinterpret_cast<const uint4*>(&l_sh[ii * DIM + head * 32]);
            u32 ea0 = 0u, ea1 = 0u, ea2 = 0u, ea3 = 0u;   // half2 zeros
#pragma unroll
            for (int qg = 0; qg < 4; qg++) {
                uint4 l4 = lrow[qg];
                u32 y0, y1, y2, y3;
                HADD2(y0, l4.x, r4[qg].x);
                HADD2(y1, l4.y, r4[qg].y);
                HADD2(y2, l4.z, r4[qg].z);
                HADD2(y3, l4.w, r4[qg].w);
                y0 &= 0x7FFF7FFFu; y1 &= 0x7FFF7FFFu;     // |.| both halves (ALU)
                y2 &= 0x7FFF7FFFu; y3 &= 0x7FFF7FFFu;
                HFMA2(ea0, ar2h[qg * 4 + 0], y0);
                HFMA2(ea1, ar2h[qg * 4 + 1], y1);
                HFMA2(ea2, ar2h[qg * 4 + 2], y2);
                HFMA2(ea3, ar2h[qg * 4 + 3], y3);
            }
            HADD2(ea0, ea0, ea1);
            HADD2(ea2, ea2, ea3);
            HADD2(ea0, ea0, ea2);
            float2 f2 = __half22float2(*reinterpret_cast<__half2*>(&ea0));
            float e = (la[ii] + ra) + (f2.x + f2.y);
            float p;
            asm("ex2.approx.f32 %0, %1;" : "=f"(p) : "f"(e));
            p = (b & (1u << ii)) ? p : 0.f;
            sl[ii] += p;
            myph[ii * 32 + lane] = __float2half_rn(p);
        }
        __syncwarp();

        // ---- agg phase on tensor pipe: ldmatrix + mma.m16n8k16 ----
#pragma unroll
        for (int ks = 0; ks < 2; ks++) {
            const __half* ap = (lg & 1) ? (p_sh + 16 * 256)
                                        : (myph + lr * 32 + ks * 16 + (lg >> 1) * 8);
            u32 sa = (u32)__cvta_generic_to_shared(ap);
            u32 a0, a1, a2, a3;
            asm volatile("ldmatrix.sync.aligned.m8n8.x4.shared.b16 {%0,%1,%2,%3}, [%4];"
                         : "=r"(a0), "=r"(a1), "=r"(a2), "=r"(a3) : "r"(sa));
#pragma unroll
            for (int nt = 0; nt < 4; nt++)
                MMA16816(dacc[nt * 4 + 0], dacc[nt * 4 + 1],
                         dacc[nt * 4 + 2], dacc[nt * 4 + 3],
                         a0, a1, a2, a3, bq[ks * 4 + nt].x, bq[ks * 4 + nt].y);
        }
        __syncwarp();   // LDSM consumed before next stage's STS overwrites p

        // rotate prefetched r-side into place
        if (t < 7) {
#pragma unroll
            for (int qg = 0; qg < 4; qg++) r4[qg] = r4n[qg];
            ra = ran;
        }
    }

    // ---- cross-warp (js) reduction ----
#pragma unroll
    for (int ii = 0; ii < I_TILE; ii++) {
        float S = sl[ii];
#pragma unroll
        for (int o = 16; o; o >>= 1) S += __shfl_xor_sync(0xffffffffu, S, o);
        if (lane == 0) sl_s[w * I_TILE + ii] = S;
    }
    // write mma accumulators: lane holds (ii = lane/4, d = nt*8 + 2*(lane%4)+{0,1})
    {
        int iw = lane >> 2, db = 2 * (lane & 3);
        float* myred = &red_s[w * 256];
#pragma unroll
        for (int nt = 0; nt < 4; nt++) {
            myred[iw * 32 + nt * 8 + db]     = dacc[nt * 4 + 0];
            myred[iw * 32 + nt * 8 + db + 1] = dacc[nt * 4 + 1];
        }
    }
    __syncthreads();

    // warp w: head' = w&3, covers ii = (w>>2) and (w>>2)+4
#pragma unroll
    for (int r = 0; r < 2; r++) {
        int ii = (w >> 2) + r * 4;
        int hh = w & 3;
        float acc = 0.f, S = 0.f;
#pragma unroll
        for (int g = 0; g < 4; g++) {
            acc += red_s[((g * 4 + hh) * I_TILE + ii) * 32 + lane];
            S   += sl_s[(g * 4 + hh) * I_TILE + ii];
        }
        o_s[ii * DIM + hh * 32 + lane] = acc * __frcp_rn(S);
    }
    __syncthreads();

    // LayerNorm + ReLU: warps 0..7 handle rows 0..7
    if (w < I_TILE) {
        int i = w;
        float v0 = o_s[i * DIM + lane];
        float v1 = o_s[i * DIM + 32 + lane];
        float v2 = o_s[i * DIM + 64 + lane];
        float v3 = o_s[i * DIM + 96 + lane];
        float sm = (v0 + v1) + (v2 + v3);
        float sq = v0 * v0 + v1 * v1 + v2 * v2 + v3 * v3;
#pragma unroll
        for (int o = 16; o; o >>= 1) {
            sm += __shfl_xor_sync(0xffffffffu, sm, o);
            sq += __shfl_xor_sync(0xffffffffu, sq, o);
        }
        float mean = sm * (1.f / 128.f);
        float var  = sq * (1.f / 128.f) - mean * mean;
        float rstd = rsqrtf(var + 1e-5f);
        float vals[4] = {v0, v1, v2, v3};
#pragma unroll
        for (int k = 0; k < 4; k++) {
            int c = 32 * k + lane;
            float y = (vals[k] - mean) * rstd * __ldg(&ln_g[c]) + __ldg(&ln_b[c]);
            out[(i0 + i) * DIM + c] = fmaxf(y, 0.f);
        }
    }
}

extern "C" void kernel_launch(void* const* d_in, const int* in_sizes, int n_in,
                              void* d_out, int out_size)
{
    const float* h   = (const float*)d_in[0];
    const int*   adj = (const int*)  d_in[1];
    const float* Wl  = (const float*)d_in[2];
    const float* Wr  = (const float*)d_in[3];
    const float* Wv  = (const float*)d_in[4];
    const float* a   = (const float*)d_in[5];
    const float* g   = (const float*)d_in[6];
    const float* b   = (const float*)d_in[7];

    const int prep_smem = (DIM * DIM + 16 * DIM) * sizeof(float);  // 72KB
    static int configured = 0;
    if (!configured) {
        cudaFuncSetAttribute(prep_kernel,
                             cudaFuncAttributeMaxDynamicSharedMemorySize, prep_smem);
        configured = 1;
    }

    prep_kernel<<<dim3(64, 3), 128, prep_smem>>>(h, Wl, Wr, Wv, a);
    gat_main<<<NN / I_TILE, 512>>>(adj, a, g, b, (float*)d_out);
}